// round 14
// baseline (speedup 1.0000x reference)
#include <cuda_runtime.h>
#include <math.h>

// ---------------------------------------------------------------------------
// Static device scratch (allocation-free rule). Zero-initialized at load.
// ---------------------------------------------------------------------------
#define MAX_M  50432
#define LC     256                 // chunk length for linear G/I scans
#define CHUNK  512                 // serial-pipeline chunk (steps)
#define NRING  4                   // smem ring depth (chunks)
#define NWIN   (NRING * CHUNK / 32)// ring capacity in 32-step windows (64)
#define TOTAL  50176               // 98*512 = 196*256, >= m-1, identity-padded

__device__ float  d_Sg[MAX_M];
__device__ float  d_Si[MAX_M];
__device__ float  d_Gl[MAX_M];
__device__ float  d_Il[MAX_M];
__device__ float  d_Gfe[256];
__device__ float  d_Ife[256];
__device__ double d_GstD[256];
__device__ double d_IstD[256];
__device__ double d_Ptab[256];
__device__ float4 d_cb4[TOTAL / 2];        // float2 view: per-step (c, b)

// ---------------------------------------------------------------------------
// Kernel 1: per-row weighted sums (L2-resident stream).
// ---------------------------------------------------------------------------
__global__ void rowdot_kernel(const float* __restrict__ spikes,
                              const float* __restrict__ w,
                              const float* __restrict__ vrev,
                              int m, int n) {
    __shared__ float4 s_aw[128];
    __shared__ float4 s_wv[128];

    const int tid  = threadIdx.x;
    const int lane = tid & 31;
    const int wrp  = tid >> 5;
    const int nv4  = n >> 2;

    for (int j = tid; j < nv4; j += blockDim.x) {
        float4 wj = reinterpret_cast<const float4*>(w)[j];
        float4 vj = reinterpret_cast<const float4*>(vrev)[j];
        float4 aw = make_float4(fabsf(wj.x), fabsf(wj.y), fabsf(wj.z), fabsf(wj.w));
        s_aw[j] = aw;
        s_wv[j] = make_float4(__fmul_rn(vj.x, aw.x), __fmul_rn(vj.y, aw.y),
                              __fmul_rn(vj.z, aw.z), __fmul_rn(vj.w, aw.w));
    }
    __syncthreads();

    const int row = blockIdx.x * (blockDim.x >> 5) + wrp;
    if (row >= m) return;

    const float4* rp = reinterpret_cast<const float4*>(spikes + (size_t)row * n);
    float accg = 0.0f, acci = 0.0f;
    for (int j = lane; j < nv4; j += 32) {
        float4 s  = rp[j];
        float4 aw = s_aw[j];
        float4 wv = s_wv[j];
        accg = fmaf(s.x, aw.x, accg); accg = fmaf(s.y, aw.y, accg);
        accg = fmaf(s.z, aw.z, accg); accg = fmaf(s.w, aw.w, accg);
        acci = fmaf(s.x, wv.x, acci); acci = fmaf(s.y, wv.y, acci);
        acci = fmaf(s.z, wv.z, acci); acci = fmaf(s.w, wv.w, acci);
    }
    for (int j = (nv4 << 2) + lane; j < n; j += 32) {
        float aw = fabsf(w[j]);
        float sv = spikes[(size_t)row * n + j];
        accg = fmaf(sv, aw, accg);
        acci = fmaf(sv, __fmul_rn(vrev[j], aw), acci);
    }

    #pragma unroll
    for (int o = 16; o > 0; o >>= 1) {
        accg += __shfl_down_sync(0xffffffffu, accg, o);
        acci += __shfl_down_sync(0xffffffffu, acci, o);
    }
    if (lane == 0) {
        d_Sg[row] = accg;
        d_Si[row] = acci;
    }
}

// ---------------------------------------------------------------------------
// Kernel 2: chunk-local forced responses (exact ref op order within chunk).
// ---------------------------------------------------------------------------
__global__ void chains_kernel(int nchunk) {
    const int c    = blockIdx.x;
    const int lane = threadIdx.x;
    const int base = c * LC;
    const float d  = expf(-0.1f);

    float sg[8], si[8];
    #pragma unroll
    for (int q = 0; q < 8; ++q) {
        sg[q] = d_Sg[base + q * 32 + lane];
        si[q] = d_Si[base + q * 32 + lane];
    }

    float G = 0.0f, I = 0.0f;
    #pragma unroll
    for (int q = 0; q < 8; ++q) {
        float gs = 0.0f, is = 0.0f;
        #pragma unroll
        for (int k = 0; k < 32; ++k) {
            const float sgk = __shfl_sync(0xffffffffu, sg[q], k);
            const float sik = __shfl_sync(0xffffffffu, si[q], k);
            if (k == lane) { gs = G; is = I; }
            G = __fmul_rn(__fadd_rn(G, sgk), d);
            I = __fmul_rn(__fadd_rn(I, sik), d);
        }
        d_Gl[base + q * 32 + lane] = gs;
        d_Il[base + q * 32 + lane] = is;
    }
    if (lane == 0) { d_Gfe[c] = G; d_Ife[c] = I; }
}

// ---------------------------------------------------------------------------
// Kernel 3: chunk carries via affine warp-scan in double + P table.
// ---------------------------------------------------------------------------
__global__ void carry_kernel(int nchunk) {     // 1 block x 64 threads
    const int tid = threadIdx.x;
    const double lg = log((double)expf(-0.1f));

    for (int j = tid; j < 256; j += 64) d_Ptab[j] = exp((double)j * lg);
    if (tid >= 32) return;

    const int    lane = tid;
    const double D    = exp((double)LC * lg);
    const int    per  = 7;
    const int    c0   = lane * per;

    double A = 1.0, Bg = 0.0, Bi = 0.0;
    for (int q = 0; q < per; ++q) {
        const int c = c0 + q;
        const double feg = (c < nchunk) ? (double)d_Gfe[c] : 0.0;
        const double fei = (c < nchunk) ? (double)d_Ife[c] : 0.0;
        A  = A * D;
        Bg = Bg * D + feg;
        Bi = Bi * D + fei;
    }
    double Ai = A, BgI = Bg, BiI = Bi;
    for (int o = 1; o < 32; o <<= 1) {
        const double A1  = __shfl_up_sync(0xffffffffu, Ai, o);
        const double Bg1 = __shfl_up_sync(0xffffffffu, BgI, o);
        const double Bi1 = __shfl_up_sync(0xffffffffu, BiI, o);
        if (lane >= o) {
            BgI = Bg1 * Ai + BgI;
            BiI = Bi1 * Ai + BiI;
            Ai  = A1 * Ai;
        }
    }
    const double hgp = __shfl_up_sync(0xffffffffu, BgI, 1);
    const double hip = __shfl_up_sync(0xffffffffu, BiI, 1);
    double Hg = (lane > 0) ? hgp : 0.0;
    double Hi = (lane > 0) ? hip : 0.0;
    for (int q = 0; q < per; ++q) {
        const int c = c0 + q;
        if (c < nchunk) {
            d_GstD[c] = Hg; d_IstD[c] = Hi;
            Hg = Hg * D + (double)d_Gfe[c];
            Hi = Hi * D + (double)d_Ife[c];
        }
    }
}

// ---------------------------------------------------------------------------
// Kernel 4: recombine + emit per-step (c,b). Pad = identity step (c=1,b=0).
// ---------------------------------------------------------------------------
__global__ void combine_kernel(float* __restrict__ vtr, int m) {
    const int i = blockIdx.x * blockDim.x + threadIdx.x;
    if (i >= TOTAL) return;
    float2* cb = reinterpret_cast<float2*>(d_cb4);

    if (i == 0) vtr[0] = 0.0f;
    if (i >= m - 1) { cb[i] = make_float2(1.0f, 0.0f); return; }

    const int c   = i >> 8;
    const int off = i & 255;
    const double P = d_Ptab[off];

    const float G = (float)((double)d_Gl[i] + d_GstD[c] * P);
    const float I = (float)((double)d_Il[i] + d_IstD[c] * P);

    const float a  = __fmul_rn(0.001f, __fadd_rn(1.0f, G));
    const float cf = __fadd_rn(1.0f, -a);
    const float b  = __fmul_rn(0.001f, I);
    cb[i] = make_float2(cf, b);
}

// ---------------------------------------------------------------------------
// Kernel 5: serial executor — ballot crossing detection.
//
// warp0: UNRESET stream U' = rn(rn(U*c)+b), bit-identical to the reference
//        step while no reset fires. Coefficients stream through two 8xfloat4
//        half-window register buffers (prefetch overlapped with the chain;
//        all indices compile-time, nothing spillable). Per-lane SEL snapshot
//        collects the 32 window values in vout; crossing detection is ONE
//        __ballot_sync(vout >= 1) + a uniform entry>=1 check per window
//        (replaces the 32-FMNMX serial side-chain: up to the FIRST true
//        crossing the clean and true paths are identical, so the clean path
//        exhibits the crossing; repaired windows chain via the entry check).
//        Rare repair replays the window with exact select semantics reading
//        coefficients from the smem ring (slot live: writer 3 chunks ahead).
// warp1: streams (c,b) global->smem ring, 3 chunks ahead.
// warp2: drains smem v ring -> vtr, 1 chunk behind.
// ---------------------------------------------------------------------------
__global__ void __launch_bounds__(96, 1) serial_kernel(float* __restrict__ vtr,
                                                       int m, int nchunks) {
    __shared__ float4 s_cb[NRING * CHUNK / 2];   // ring: NWIN windows x 16 f4
    __shared__ float  s_v [NRING * CHUNK];

    const int wid  = threadIdx.x >> 5;
    const int lane = threadIdx.x & 31;

    if (threadIdx.x == 0) vtr[0] = 0.0f;

    // prefill cb chunks 0..2
    if (wid == 1) {
        for (int c = 0; c < 3 && c < nchunks; ++c) {
            const float4* src = d_cb4 + c * (CHUNK / 2);
            #pragma unroll
            for (int j = 0; j < CHUNK / 2 / 32; ++j)
                s_cb[c * (CHUNK / 2) + j * 32 + lane] = src[j * 32 + lane];
        }
    }
    __syncthreads();

    float  U = 0.0f;
    float4 qA[8], qB[8];

    if (wid == 0) {                     // preload half A of window 0
        #pragma unroll
        for (int j = 0; j < 8; ++j) qA[j] = s_cb[j];
    }

    for (int t = 0; t < nchunks; ++t) {
        if (wid == 0) {
            const int w0 = t * 16;      // global window index of this chunk
            for (int p = 0; p < 16; ++p) {          // NOT unrolled (I-cache)
                const int gw = w0 + p;
                const int rw = gw & (NWIN - 1);     // ring window slot

                // prefetch half B of this window (overlaps chain A)
                #pragma unroll
                for (int j = 0; j < 8; ++j) qB[j] = s_cb[rw * 16 + 8 + j];

                const float entry = U;
                float vout = 0.0f;

                // ---- chain half A: steps 0..15 (lanes 0..15 snapshot) ----
                #pragma unroll
                for (int j = 0; j < 8; ++j) {
                    U = __fadd_rn(__fmul_rn(U, qA[j].x), qA[j].y);
                    vout = (2 * j == lane) ? U : vout;
                    U = __fadd_rn(__fmul_rn(U, qA[j].z), qA[j].w);
                    vout = (2 * j + 1 == lane) ? U : vout;
                }

                // prefetch half A of NEXT window (overlaps chain B)
                {
                    const int nrw = (gw + 1) & (NWIN - 1);
                    #pragma unroll
                    for (int j = 0; j < 8; ++j) qA[j] = s_cb[nrw * 16 + j];
                }

                // ---- chain half B: steps 16..31 (lanes 16..31 snapshot) --
                #pragma unroll
                for (int j = 0; j < 8; ++j) {
                    U = __fadd_rn(__fmul_rn(U, qB[j].x), qB[j].y);
                    vout = (16 + 2 * j == lane) ? U : vout;
                    U = __fadd_rn(__fmul_rn(U, qB[j].z), qB[j].w);
                    vout = (16 + 2 * j + 1 == lane) ? U : vout;
                }

                // ---- crossing detection: one ballot per window ----------
                const unsigned crossed =
                    __ballot_sync(0xffffffffu, vout >= 1.0f);
                if (crossed || entry >= 1.0f) {
                    // rare repair: exact select semantics, coeffs from smem
                    const float2* cb2 =
                        reinterpret_cast<const float2*>(s_cb) + rw * 32;
                    float v = entry;
                    #pragma unroll 4
                    for (int k = 0; k < 32; ++k) {
                        const float2 cb = cb2[k];
                        const float u = __fadd_rn(__fmul_rn(v, cb.x), cb.y);
                        v = (v < 1.0f) ? u : 0.0f;
                        vout = (k == lane) ? v : vout;
                    }
                    U = v;
                }

                s_v[rw * 32 + lane] = vout;         // one coalesced STS
            }
        } else if (wid == 1) {
            const int f = t + 3;
            if (f < nchunks) {
                const int dst = (f & (NRING - 1)) * (CHUNK / 2);
                const float4* src = d_cb4 + f * (CHUNK / 2);
                #pragma unroll
                for (int j = 0; j < CHUNK / 2 / 32; ++j)
                    s_cb[dst + j * 32 + lane] = src[j * 32 + lane];
            }
        } else if (wid == 2) {
            if (t >= 1) {
                const int d   = t - 1;
                const int src = (d & (NRING - 1)) * CHUNK;
                #pragma unroll
                for (int j = 0; j < CHUNK / 32; ++j) {
                    const int i = d * CHUNK + j * 32 + lane + 1;
                    if (i < m) vtr[i] = s_v[src + j * 32 + lane];
                }
            }
        }
        __syncthreads();
    }
    // drain the final chunk
    if (wid == 2) {
        const int d   = nchunks - 1;
        const int src = (d & (NRING - 1)) * CHUNK;
        #pragma unroll
        for (int j = 0; j < CHUNK / 32; ++j) {
            const int i = d * CHUNK + j * 32 + lane + 1;
            if (i < m) vtr[i] = s_v[src + j * 32 + lane];
        }
    }
}

// ---------------------------------------------------------------------------
extern "C" void kernel_launch(void* const* d_in, const int* in_sizes, int n_in,
                              void* d_out, int out_size) {
    const float* spikes = (const float*)d_in[0];
    const float* w      = (const float*)d_in[1];
    const float* vrev   = (const float*)d_in[2];
    float*       vtr    = (float*)d_out;

    const int n = in_sizes[1];                       // 500
    const int m = in_sizes[0] / n;                   // 50000
    const int nchunk  = (m + LC - 1) / LC;           // 196
    const int nchunks = TOTAL / CHUNK;               // 98

    rowdot_kernel<<<(m + 7) / 8, 256>>>(spikes, w, vrev, m, n);
    chains_kernel<<<nchunk, 32>>>(nchunk);
    carry_kernel<<<1, 64>>>(nchunk);
    combine_kernel<<<(TOTAL + 255) / 256, 256>>>(vtr, m);
    serial_kernel<<<1, 96>>>(vtr, m, nchunks);
}

// round 15
// speedup vs baseline: 1.6391x; 1.6391x over previous
#include <cuda_runtime.h>
#include <math.h>

// ---------------------------------------------------------------------------
// Static device scratch (allocation-free rule). Zero-initialized at load.
// ---------------------------------------------------------------------------
#define MAX_M  50432
#define LC     256                 // chunk length for linear G/I scans
#define CHUNK  512                 // serial-pipeline chunk (steps)
#define NRING  4                   // smem ring depth (chunks)
#define NWIN   (NRING * CHUNK / 32)// ring capacity in 32-step windows (64)
#define TOTAL  50176               // 98*512 = 196*256, >= m-1, identity-padded

__device__ float  d_Sg[MAX_M];
__device__ float  d_Si[MAX_M];
__device__ float  d_Gl[MAX_M];
__device__ float  d_Il[MAX_M];
__device__ float  d_Gfe[256];
__device__ float  d_Ife[256];
__device__ double d_GstD[256];
__device__ double d_IstD[256];
__device__ double d_Ptab[256];
__device__ float4 d_cb4[TOTAL / 2];        // float2 view: per-step (c, b)

// ---------------------------------------------------------------------------
// Kernel 1: per-row weighted sums (L2-resident stream).
// ---------------------------------------------------------------------------
__global__ void rowdot_kernel(const float* __restrict__ spikes,
                              const float* __restrict__ w,
                              const float* __restrict__ vrev,
                              int m, int n) {
    __shared__ float4 s_aw[128];
    __shared__ float4 s_wv[128];

    const int tid  = threadIdx.x;
    const int lane = tid & 31;
    const int wrp  = tid >> 5;
    const int nv4  = n >> 2;

    for (int j = tid; j < nv4; j += blockDim.x) {
        float4 wj = reinterpret_cast<const float4*>(w)[j];
        float4 vj = reinterpret_cast<const float4*>(vrev)[j];
        float4 aw = make_float4(fabsf(wj.x), fabsf(wj.y), fabsf(wj.z), fabsf(wj.w));
        s_aw[j] = aw;
        s_wv[j] = make_float4(__fmul_rn(vj.x, aw.x), __fmul_rn(vj.y, aw.y),
                              __fmul_rn(vj.z, aw.z), __fmul_rn(vj.w, aw.w));
    }
    __syncthreads();

    const int row = blockIdx.x * (blockDim.x >> 5) + wrp;
    if (row >= m) return;

    const float4* rp = reinterpret_cast<const float4*>(spikes + (size_t)row * n);
    float accg = 0.0f, acci = 0.0f;
    for (int j = lane; j < nv4; j += 32) {
        float4 s  = rp[j];
        float4 aw = s_aw[j];
        float4 wv = s_wv[j];
        accg = fmaf(s.x, aw.x, accg); accg = fmaf(s.y, aw.y, accg);
        accg = fmaf(s.z, aw.z, accg); accg = fmaf(s.w, aw.w, accg);
        acci = fmaf(s.x, wv.x, acci); acci = fmaf(s.y, wv.y, acci);
        acci = fmaf(s.z, wv.z, acci); acci = fmaf(s.w, wv.w, acci);
    }
    for (int j = (nv4 << 2) + lane; j < n; j += 32) {
        float aw = fabsf(w[j]);
        float sv = spikes[(size_t)row * n + j];
        accg = fmaf(sv, aw, accg);
        acci = fmaf(sv, __fmul_rn(vrev[j], aw), acci);
    }

    #pragma unroll
    for (int o = 16; o > 0; o >>= 1) {
        accg += __shfl_down_sync(0xffffffffu, accg, o);
        acci += __shfl_down_sync(0xffffffffu, acci, o);
    }
    if (lane == 0) {
        d_Sg[row] = accg;
        d_Si[row] = acci;
    }
}

// ---------------------------------------------------------------------------
// Kernel 2: chunk-local forced responses (exact ref op order within chunk).
// ---------------------------------------------------------------------------
__global__ void chains_kernel(int nchunk) {
    const int c    = blockIdx.x;
    const int lane = threadIdx.x;
    const int base = c * LC;
    const float d  = expf(-0.1f);

    float sg[8], si[8];
    #pragma unroll
    for (int q = 0; q < 8; ++q) {
        sg[q] = d_Sg[base + q * 32 + lane];
        si[q] = d_Si[base + q * 32 + lane];
    }

    float G = 0.0f, I = 0.0f;
    #pragma unroll
    for (int q = 0; q < 8; ++q) {
        float gs = 0.0f, is = 0.0f;
        #pragma unroll
        for (int k = 0; k < 32; ++k) {
            const float sgk = __shfl_sync(0xffffffffu, sg[q], k);
            const float sik = __shfl_sync(0xffffffffu, si[q], k);
            if (k == lane) { gs = G; is = I; }
            G = __fmul_rn(__fadd_rn(G, sgk), d);
            I = __fmul_rn(__fadd_rn(I, sik), d);
        }
        d_Gl[base + q * 32 + lane] = gs;
        d_Il[base + q * 32 + lane] = is;
    }
    if (lane == 0) { d_Gfe[c] = G; d_Ife[c] = I; }
}

// ---------------------------------------------------------------------------
// Kernel 3: chunk carries via affine warp-scan in double + P table.
// ---------------------------------------------------------------------------
__global__ void carry_kernel(int nchunk) {     // 1 block x 64 threads
    const int tid = threadIdx.x;
    const double lg = log((double)expf(-0.1f));

    for (int j = tid; j < 256; j += 64) d_Ptab[j] = exp((double)j * lg);
    if (tid >= 32) return;

    const int    lane = tid;
    const double D    = exp((double)LC * lg);
    const int    per  = 7;
    const int    c0   = lane * per;

    double A = 1.0, Bg = 0.0, Bi = 0.0;
    for (int q = 0; q < per; ++q) {
        const int c = c0 + q;
        const double feg = (c < nchunk) ? (double)d_Gfe[c] : 0.0;
        const double fei = (c < nchunk) ? (double)d_Ife[c] : 0.0;
        A  = A * D;
        Bg = Bg * D + feg;
        Bi = Bi * D + fei;
    }
    double Ai = A, BgI = Bg, BiI = Bi;
    for (int o = 1; o < 32; o <<= 1) {
        const double A1  = __shfl_up_sync(0xffffffffu, Ai, o);
        const double Bg1 = __shfl_up_sync(0xffffffffu, BgI, o);
        const double Bi1 = __shfl_up_sync(0xffffffffu, BiI, o);
        if (lane >= o) {
            BgI = Bg1 * Ai + BgI;
            BiI = Bi1 * Ai + BiI;
            Ai  = A1 * Ai;
        }
    }
    const double hgp = __shfl_up_sync(0xffffffffu, BgI, 1);
    const double hip = __shfl_up_sync(0xffffffffu, BiI, 1);
    double Hg = (lane > 0) ? hgp : 0.0;
    double Hi = (lane > 0) ? hip : 0.0;
    for (int q = 0; q < per; ++q) {
        const int c = c0 + q;
        if (c < nchunk) {
            d_GstD[c] = Hg; d_IstD[c] = Hi;
            Hg = Hg * D + (double)d_Gfe[c];
            Hi = Hi * D + (double)d_Ife[c];
        }
    }
}

// ---------------------------------------------------------------------------
// Kernel 4: recombine + emit per-step (c,b). Pad = identity step (c=1,b=0).
// ---------------------------------------------------------------------------
__global__ void combine_kernel(float* __restrict__ vtr, int m) {
    const int i = blockIdx.x * blockDim.x + threadIdx.x;
    if (i >= TOTAL) return;
    float2* cb = reinterpret_cast<float2*>(d_cb4);

    if (i == 0) vtr[0] = 0.0f;
    if (i >= m - 1) { cb[i] = make_float2(1.0f, 0.0f); return; }

    const int c   = i >> 8;
    const int off = i & 255;
    const double P = d_Ptab[off];

    const float G = (float)((double)d_Gl[i] + d_GstD[c] * P);
    const float I = (float)((double)d_Il[i] + d_IstD[c] * P);

    const float a  = __fmul_rn(0.001f, __fadd_rn(1.0f, G));
    const float cf = __fadd_rn(1.0f, -a);
    const float b  = __fmul_rn(0.001f, I);
    cb[i] = make_float2(cf, b);
}

// ---------------------------------------------------------------------------
// Kernel 5: serial executor — per-step STS, split-FMNMX side chain.
//
// warp0: UNRESET stream U' = rn(rn(U*c)+b), bit-identical to the reference
//        step while no reset fires. Coefficients stream through two 8xfloat4
//        half-window register buffers (prefetch overlapped with the chain;
//        all indices compile-time, nothing spillable — the proven R13
//        layout). Each step's value leaves via ONE same-address STS from all
//        lanes (one wavefront, LSU pipe — replaces the ISETP+SEL snapshot
//        that contended the alu pipe). Crossing detection: FMNMX side chain
//        SPLIT into two interleaved accumulators (vm0 even / vm1 odd steps,
//        both seeded with the window entry) so each FMNMX has 8 cycles of
//        slack instead of 4; merged once at window end. Rare repair replays
//        the window with exact select semantics reading coefficients from
//        the smem ring (slot live: writer 3 chunks ahead in a 4-deep ring).
// warp1: streams (c,b) global->smem ring, 3 chunks ahead.
// warp2: drains smem v ring -> vtr, 1 chunk behind.
// ---------------------------------------------------------------------------
__global__ void __launch_bounds__(96, 1) serial_kernel(float* __restrict__ vtr,
                                                       int m, int nchunks) {
    __shared__ float4 s_cb[NRING * CHUNK / 2];   // ring: NWIN windows x 16 f4
    __shared__ float  s_v [NRING * CHUNK];

    const int wid  = threadIdx.x >> 5;
    const int lane = threadIdx.x & 31;

    if (threadIdx.x == 0) vtr[0] = 0.0f;

    // prefill cb chunks 0..2
    if (wid == 1) {
        for (int c = 0; c < 3 && c < nchunks; ++c) {
            const float4* src = d_cb4 + c * (CHUNK / 2);
            #pragma unroll
            for (int j = 0; j < CHUNK / 2 / 32; ++j)
                s_cb[c * (CHUNK / 2) + j * 32 + lane] = src[j * 32 + lane];
        }
    }
    __syncthreads();

    float  U = 0.0f;
    float4 qA[8], qB[8];

    if (wid == 0) {                     // preload half A of window 0
        #pragma unroll
        for (int j = 0; j < 8; ++j) qA[j] = s_cb[j];
    }

    for (int t = 0; t < nchunks; ++t) {
        if (wid == 0) {
            const int w0 = t * 16;      // global window index of this chunk
            for (int p = 0; p < 16; ++p) {          // NOT unrolled (I-cache)
                const int gw = w0 + p;
                const int rw = gw & (NWIN - 1);     // ring window slot
                float* const sv = s_v + rw * 32;

                // prefetch half B of this window (overlaps chain A)
                #pragma unroll
                for (int j = 0; j < 8; ++j) qB[j] = s_cb[rw * 16 + 8 + j];

                const float entry = U;
                float vm0 = U, vm1 = U;             // both include entry

                // ---- chain half A: steps 0..15 ----
                #pragma unroll
                for (int j = 0; j < 8; ++j) {
                    U = __fadd_rn(__fmul_rn(U, qA[j].x), qA[j].y);
                    vm0 = fmaxf(vm0, U);
                    sv[2 * j] = U;                  // one wavefront (same addr)
                    U = __fadd_rn(__fmul_rn(U, qA[j].z), qA[j].w);
                    vm1 = fmaxf(vm1, U);
                    sv[2 * j + 1] = U;
                }

                // prefetch half A of NEXT window (overlaps chain B)
                {
                    const int nrw = (gw + 1) & (NWIN - 1);
                    #pragma unroll
                    for (int j = 0; j < 8; ++j) qA[j] = s_cb[nrw * 16 + j];
                }

                // ---- chain half B: steps 16..31 ----
                #pragma unroll
                for (int j = 0; j < 8; ++j) {
                    U = __fadd_rn(__fmul_rn(U, qB[j].x), qB[j].y);
                    vm0 = fmaxf(vm0, U);
                    sv[16 + 2 * j] = U;
                    U = __fadd_rn(__fmul_rn(U, qB[j].z), qB[j].w);
                    vm1 = fmaxf(vm1, U);
                    sv[16 + 2 * j + 1] = U;
                }

                // ---- rare repair: exact select semantics, coeffs from smem
                if (fmaxf(vm0, vm1) >= 1.0f) {
                    const float2* cb2 =
                        reinterpret_cast<const float2*>(s_cb) + rw * 32;
                    float v = entry;
                    #pragma unroll 4
                    for (int k = 0; k < 32; ++k) {
                        const float2 cb = cb2[k];
                        const float u = __fadd_rn(__fmul_rn(v, cb.x), cb.y);
                        v = (v < 1.0f) ? u : 0.0f;
                        sv[k] = v;
                    }
                    U = v;
                }
            }
        } else if (wid == 1) {
            const int f = t + 3;
            if (f < nchunks) {
                const int dst = (f & (NRING - 1)) * (CHUNK / 2);
                const float4* src = d_cb4 + f * (CHUNK / 2);
                #pragma unroll
                for (int j = 0; j < CHUNK / 2 / 32; ++j)
                    s_cb[dst + j * 32 + lane] = src[j * 32 + lane];
            }
        } else if (wid == 2) {
            if (t >= 1) {
                const int d   = t - 1;
                const int src = (d & (NRING - 1)) * CHUNK;
                #pragma unroll
                for (int j = 0; j < CHUNK / 32; ++j) {
                    const int i = d * CHUNK + j * 32 + lane + 1;
                    if (i < m) vtr[i] = s_v[src + j * 32 + lane];
                }
            }
        }
        __syncthreads();
    }
    // drain the final chunk
    if (wid == 2) {
        const int d   = nchunks - 1;
        const int src = (d & (NRING - 1)) * CHUNK;
        #pragma unroll
        for (int j = 0; j < CHUNK / 32; ++j) {
            const int i = d * CHUNK + j * 32 + lane + 1;
            if (i < m) vtr[i] = s_v[src + j * 32 + lane];
        }
    }
}

// ---------------------------------------------------------------------------
extern "C" void kernel_launch(void* const* d_in, const int* in_sizes, int n_in,
                              void* d_out, int out_size) {
    const float* spikes = (const float*)d_in[0];
    const float* w      = (const float*)d_in[1];
    const float* vrev   = (const float*)d_in[2];
    float*       vtr    = (float*)d_out;

    const int n = in_sizes[1];                       // 500
    const int m = in_sizes[0] / n;                   // 50000
    const int nchunk  = (m + LC - 1) / LC;           // 196
    const int nchunks = TOTAL / CHUNK;               // 98

    rowdot_kernel<<<(m + 7) / 8, 256>>>(spikes, w, vrev, m, n);
    chains_kernel<<<nchunk, 32>>>(nchunk);
    carry_kernel<<<1, 64>>>(nchunk);
    combine_kernel<<<(TOTAL + 255) / 256, 256>>>(vtr, m);
    serial_kernel<<<1, 96>>>(vtr, m, nchunks);
}

// round 17
// speedup vs baseline: 3.5772x; 2.1824x over previous
#include <cuda_runtime.h>
#include <math.h>

// ---------------------------------------------------------------------------
// Static device scratch (allocation-free rule). Zero-initialized at load.
// ---------------------------------------------------------------------------
#define MAX_M  50432
#define LC     256                 // chunk length for linear G/I scans
#define CHUNK  512                 // serial-pipeline chunk (steps)
#define NRING  4                   // smem ring depth (chunks)
#define TOTAL  50176               // 98*512 = 196*256, >= m-1, identity-padded
#define NWINT  (TOTAL / 32)        // 1568 windows of 32 steps

__device__ float  d_Sg[MAX_M];
__device__ float  d_Si[MAX_M];
__device__ float  d_Gl[MAX_M];
__device__ float  d_Il[MAX_M];
__device__ float  d_Gfe[256];
__device__ float  d_Ife[256];
__device__ double d_GstD[256];
__device__ double d_IstD[256];
__device__ double d_Ptab[256];
__device__ float4 d_cb4[TOTAL / 2];        // float2 view: per-step (c, b)
__device__ float4 d_AB4[TOTAL / 2];        // float2 view: window prefix (A_k, B_k)
__device__ float4 d_WC[NWINT];             // per window {A31, B31, VcritGuard, 0}

// ---------------------------------------------------------------------------
// Kernel 1: per-row weighted sums (L2-resident stream).
// ---------------------------------------------------------------------------
__global__ void rowdot_kernel(const float* __restrict__ spikes,
                              const float* __restrict__ w,
                              const float* __restrict__ vrev,
                              int m, int n) {
    __shared__ float4 s_aw[128];
    __shared__ float4 s_wv[128];

    const int tid  = threadIdx.x;
    const int lane = tid & 31;
    const int wrp  = tid >> 5;
    const int nv4  = n >> 2;

    for (int j = tid; j < nv4; j += blockDim.x) {
        float4 wj = reinterpret_cast<const float4*>(w)[j];
        float4 vj = reinterpret_cast<const float4*>(vrev)[j];
        float4 aw = make_float4(fabsf(wj.x), fabsf(wj.y), fabsf(wj.z), fabsf(wj.w));
        s_aw[j] = aw;
        s_wv[j] = make_float4(__fmul_rn(vj.x, aw.x), __fmul_rn(vj.y, aw.y),
                              __fmul_rn(vj.z, aw.z), __fmul_rn(vj.w, aw.w));
    }
    __syncthreads();

    const int row = blockIdx.x * (blockDim.x >> 5) + wrp;
    if (row >= m) return;

    const float4* rp = reinterpret_cast<const float4*>(spikes + (size_t)row * n);
    float accg = 0.0f, acci = 0.0f;
    for (int j = lane; j < nv4; j += 32) {
        float4 s  = rp[j];
        float4 aw = s_aw[j];
        float4 wv = s_wv[j];
        accg = fmaf(s.x, aw.x, accg); accg = fmaf(s.y, aw.y, accg);
        accg = fmaf(s.z, aw.z, accg); accg = fmaf(s.w, aw.w, accg);
        acci = fmaf(s.x, wv.x, acci); acci = fmaf(s.y, wv.y, acci);
        acci = fmaf(s.z, wv.z, acci); acci = fmaf(s.w, wv.w, acci);
    }
    for (int j = (nv4 << 2) + lane; j < n; j += 32) {
        float aw = fabsf(w[j]);
        float sv = spikes[(size_t)row * n + j];
        accg = fmaf(sv, aw, accg);
        acci = fmaf(sv, __fmul_rn(vrev[j], aw), acci);
    }

    #pragma unroll
    for (int o = 16; o > 0; o >>= 1) {
        accg += __shfl_down_sync(0xffffffffu, accg, o);
        acci += __shfl_down_sync(0xffffffffu, acci, o);
    }
    if (lane == 0) {
        d_Sg[row] = accg;
        d_Si[row] = acci;
    }
}

// ---------------------------------------------------------------------------
// Kernel 2: chunk-local forced responses (exact ref op order within chunk).
// ---------------------------------------------------------------------------
__global__ void chains_kernel(int nchunk) {
    const int c    = blockIdx.x;
    const int lane = threadIdx.x;
    const int base = c * LC;
    const float d  = expf(-0.1f);

    float sg[8], si[8];
    #pragma unroll
    for (int q = 0; q < 8; ++q) {
        sg[q] = d_Sg[base + q * 32 + lane];
        si[q] = d_Si[base + q * 32 + lane];
    }

    float G = 0.0f, I = 0.0f;
    #pragma unroll
    for (int q = 0; q < 8; ++q) {
        float gs = 0.0f, is = 0.0f;
        #pragma unroll
        for (int k = 0; k < 32; ++k) {
            const float sgk = __shfl_sync(0xffffffffu, sg[q], k);
            const float sik = __shfl_sync(0xffffffffu, si[q], k);
            if (k == lane) { gs = G; is = I; }
            G = __fmul_rn(__fadd_rn(G, sgk), d);
            I = __fmul_rn(__fadd_rn(I, sik), d);
        }
        d_Gl[base + q * 32 + lane] = gs;
        d_Il[base + q * 32 + lane] = is;
    }
    if (lane == 0) { d_Gfe[c] = G; d_Ife[c] = I; }
}

// ---------------------------------------------------------------------------
// Kernel 3: chunk carries via affine warp-scan in double + P table.
// ---------------------------------------------------------------------------
__global__ void carry_kernel(int nchunk) {     // 1 block x 64 threads
    const int tid = threadIdx.x;
    const double lg = log((double)expf(-0.1f));

    for (int j = tid; j < 256; j += 64) d_Ptab[j] = exp((double)j * lg);
    if (tid >= 32) return;

    const int    lane = tid;
    const double D    = exp((double)LC * lg);
    const int    per  = 7;
    const int    c0   = lane * per;

    double A = 1.0, Bg = 0.0, Bi = 0.0;
    for (int q = 0; q < per; ++q) {
        const int c = c0 + q;
        const double feg = (c < nchunk) ? (double)d_Gfe[c] : 0.0;
        const double fei = (c < nchunk) ? (double)d_Ife[c] : 0.0;
        A  = A * D;
        Bg = Bg * D + feg;
        Bi = Bi * D + fei;
    }
    double Ai = A, BgI = Bg, BiI = Bi;
    for (int o = 1; o < 32; o <<= 1) {
        const double A1  = __shfl_up_sync(0xffffffffu, Ai, o);
        const double Bg1 = __shfl_up_sync(0xffffffffu, BgI, o);
        const double Bi1 = __shfl_up_sync(0xffffffffu, BiI, o);
        if (lane >= o) {
            BgI = Bg1 * Ai + BgI;
            BiI = Bi1 * Ai + BiI;
            Ai  = A1 * Ai;
        }
    }
    const double hgp = __shfl_up_sync(0xffffffffu, BgI, 1);
    const double hip = __shfl_up_sync(0xffffffffu, BiI, 1);
    double Hg = (lane > 0) ? hgp : 0.0;
    double Hi = (lane > 0) ? hip : 0.0;
    for (int q = 0; q < per; ++q) {
        const int c = c0 + q;
        if (c < nchunk) {
            d_GstD[c] = Hg; d_IstD[c] = Hi;
            Hg = Hg * D + (double)d_Gfe[c];
            Hi = Hi * D + (double)d_Ife[c];
        }
    }
}

// ---------------------------------------------------------------------------
// Kernel 4: recombine + emit per-step (c,b). Pad = identity step (c=1,b=0).
// ---------------------------------------------------------------------------
__global__ void combine_kernel(float* __restrict__ vtr, int m) {
    const int i = blockIdx.x * blockDim.x + threadIdx.x;
    if (i >= TOTAL) return;
    float2* cb = reinterpret_cast<float2*>(d_cb4);

    if (i == 0) vtr[0] = 0.0f;
    if (i >= m - 1) { cb[i] = make_float2(1.0f, 0.0f); return; }

    const int c   = i >> 8;
    const int off = i & 255;
    const double P = d_Ptab[off];

    const float G = (float)((double)d_Gl[i] + d_GstD[c] * P);
    const float I = (float)((double)d_Il[i] + d_IstD[c] * P);

    const float a  = __fmul_rn(0.001f, __fadd_rn(1.0f, G));
    const float cf = __fadd_rn(1.0f, -a);
    const float b  = __fmul_rn(0.001f, I);
    cb[i] = make_float2(cf, b);
}

// ---------------------------------------------------------------------------
// Kernel 4b: window prefix maps. One thread per 32-step window.
//   A_k = prod_{j<=k} c_j, B_k = B_{k-1}*c_k + b_k   (double, rounded once)
//   v_{entry+k+1} = v_entry*A_k + B_k  (valid while no reset fires)
//   VcritGuard = min( min_k (1-B_k)/A_k - 1e-5, 1 - 1e-5 )
//   => window needs exact repair iff entry v >= VcritGuard (conservative:
//      composed-vs-exact noise ~3e-7 << 1e-5 guard; clamp covers entry>=1).
// ---------------------------------------------------------------------------
__global__ void abprep_kernel() {
    const int w = blockIdx.x * blockDim.x + threadIdx.x;
    if (w >= NWINT) return;

    const float2* cb = reinterpret_cast<const float2*>(d_cb4) + w * 32;
    float2*       ab = reinterpret_cast<float2*>(d_AB4) + w * 32;

    double A = 1.0, B = 0.0, vcrit = 1e30;
    for (int k = 0; k < 32; ++k) {
        const float2 c = cb[k];
        A = A * (double)c.x;
        B = B * (double)c.x + (double)c.y;
        ab[k] = make_float2((float)A, (float)B);
        const double t = (1.0 - B) / A;
        if (t < vcrit) vcrit = t;
    }
    const float vg = (float)fmin(vcrit - 1e-5, 1.0 - 1e-5);
    d_WC[w] = make_float4((float)A, (float)B, vg, 0.0f);
}

// ---------------------------------------------------------------------------
// Kernel 5: serial executor over WINDOW maps (1568 links instead of 50176).
//
// warp0: per 32-step window: v' = rn(rn(v*A31)+B31) — 8-cyc chain per 32
//        steps. Lane k emits output v*A_k+B_k (off-path, coalesced STS).
//        ONE uniform compare v >= VcritGuard (no vote, no cross-lane
//        traffic) triggers the rare exact-select sequential repair from the
//        smem cb ring (proven R10-R15 path; restores exact post-reset state
//        since reset yields bitwise 0). Window (A,B,Vcrit) buffers are
//        register double-buffered by parity, reloaded 2 windows ahead.
// warp1: streams (A,B), (c,b), WC global->smem ring, 3 chunks ahead.
// warp2: drains smem v ring -> vtr, 1 chunk behind.
// ---------------------------------------------------------------------------
__global__ void __launch_bounds__(96, 1) serial_kernel(float* __restrict__ vtr,
                                                       int m, int nchunks) {
    __shared__ float4 s_ab4 [NRING * CHUNK / 2];  // window prefix maps
    __shared__ float4 s_cb4s[NRING * CHUNK / 2];  // per-step (c,b) for repair
    __shared__ float4 s_wc  [NRING * 16];         // per-window {A31,B31,Vc,_}
    __shared__ float  s_v   [NRING * CHUNK];

    const int wid  = threadIdx.x >> 5;
    const int lane = threadIdx.x & 31;

    const float2* s_ab2 = reinterpret_cast<const float2*>(s_ab4);
    const float2* s_cb2 = reinterpret_cast<const float2*>(s_cb4s);

    if (threadIdx.x == 0) vtr[0] = 0.0f;

    // prefill chunks 0..2
    if (wid == 1) {
        for (int c = 0; c < 3 && c < nchunks; ++c) {
            const float4* sa = d_AB4 + c * (CHUNK / 2);
            const float4* sc = d_cb4 + c * (CHUNK / 2);
            #pragma unroll
            for (int j = 0; j < CHUNK / 2 / 32; ++j) {
                s_ab4 [c * (CHUNK / 2) + j * 32 + lane] = sa[j * 32 + lane];
                s_cb4s[c * (CHUNK / 2) + j * 32 + lane] = sc[j * 32 + lane];
            }
            if (lane < 16) s_wc[c * 16 + lane] = d_WC[c * 16 + lane];
        }
    }
    __syncthreads();

    float  v = 0.0f;
    int    gw = 0;                       // persistent global window counter
    float2 ab0, ab1;
    float4 wc0, wc1;

    if (wid == 0) {                      // preload windows 0 and 1
        ab0 = s_ab2[0 * 32 + lane];  wc0 = s_wc[0];
        ab1 = s_ab2[1 * 32 + lane];  wc1 = s_wc[1];
    }

#define WIN_STEP(AB, WC) do {                                          \
    const int rw_ = gw & 63;                                           \
    const bool  bad_ = (v >= (WC).z);                                  \
    const float vk_  = __fadd_rn(__fmul_rn(v, (AB).x), (AB).y);        \
    float       vn_  = __fadd_rn(__fmul_rn(v, (WC).x), (WC).y);        \
    s_v[rw_ * 32 + lane] = vk_;                                        \
    { const int nr_ = (gw + 2) & 63;                                   \
      (AB) = s_ab2[nr_ * 32 + lane];                                   \
      (WC) = s_wc[nr_]; }                                              \
    if (bad_) {                                                        \
        const float2* cbp_ = s_cb2 + rw_ * 32;                         \
        float vv_ = v;                                                 \
        _Pragma("unroll 4")                                            \
        for (int k_ = 0; k_ < 32; ++k_) {                              \
            const float2 cb_ = cbp_[k_];                               \
            const float  u_  = __fadd_rn(__fmul_rn(vv_, cb_.x), cb_.y);\
            vv_ = (vv_ < 1.0f) ? u_ : 0.0f;                            \
            s_v[rw_ * 32 + k_] = vv_;                                  \
        }                                                              \
        vn_ = vv_;                                                     \
    }                                                                  \
    v = vn_;                                                           \
    ++gw;                                                              \
} while (0)

    for (int t = 0; t < nchunks; ++t) {
        if (wid == 0) {
            for (int p = 0; p < 16; p += 2) {       // 16 windows per chunk
                WIN_STEP(ab0, wc0);
                WIN_STEP(ab1, wc1);
            }
        } else if (wid == 1) {
            const int f = t + 3;
            if (f < nchunks) {
                const int dst = (f & (NRING - 1)) * (CHUNK / 2);
                const float4* sa = d_AB4 + f * (CHUNK / 2);
                const float4* sc = d_cb4 + f * (CHUNK / 2);
                #pragma unroll
                for (int j = 0; j < CHUNK / 2 / 32; ++j) {
                    s_ab4 [dst + j * 32 + lane] = sa[j * 32 + lane];
                    s_cb4s[dst + j * 32 + lane] = sc[j * 32 + lane];
                }
                if (lane < 16)
                    s_wc[(f & (NRING - 1)) * 16 + lane] = d_WC[f * 16 + lane];
            }
        } else if (wid == 2) {
            if (t >= 1) {
                const int d   = t - 1;
                const int src = (d & (NRING - 1)) * CHUNK;
                #pragma unroll
                for (int j = 0; j < CHUNK / 32; ++j) {
                    const int i = d * CHUNK + j * 32 + lane + 1;
                    if (i < m) vtr[i] = s_v[src + j * 32 + lane];
                }
            }
        }
        __syncthreads();
    }
    // drain the final chunk
    if (wid == 2) {
        const int d   = nchunks - 1;
        const int src = (d & (NRING - 1)) * CHUNK;
        #pragma unroll
        for (int j = 0; j < CHUNK / 32; ++j) {
            const int i = d * CHUNK + j * 32 + lane + 1;
            if (i < m) vtr[i] = s_v[src + j * 32 + lane];
        }
    }
#undef WIN_STEP
}

// ---------------------------------------------------------------------------
extern "C" void kernel_launch(void* const* d_in, const int* in_sizes, int n_in,
                              void* d_out, int out_size) {
    const float* spikes = (const float*)d_in[0];
    const float* w      = (const float*)d_in[1];
    const float* vrev   = (const float*)d_in[2];
    float*       vtr    = (float*)d_out;

    const int n = in_sizes[1];                       // 500
    const int m = in_sizes[0] / n;                   // 50000
    const int nchunk  = (m + LC - 1) / LC;           // 196
    const int nchunks = TOTAL / CHUNK;               // 98

    rowdot_kernel<<<(m + 7) / 8, 256>>>(spikes, w, vrev, m, n);
    chains_kernel<<<nchunk, 32>>>(nchunk);
    carry_kernel<<<1, 64>>>(nchunk);
    combine_kernel<<<(TOTAL + 255) / 256, 256>>>(vtr, m);
    abprep_kernel<<<(NWINT + 127) / 128, 128>>>();
    serial_kernel<<<1, 96>>>(vtr, m, nchunks);
}